// round 10
// baseline (speedup 1.0000x reference)
#include <cuda_runtime.h>
#include <cuda_fp16.h>
#include <cstdint>

#define T_DIM  4096
#define C_DIM  2048
#define K_DIM  2048
#define S_CHUNKS 32
#define L_CHUNK  128

#define KTILE  64
#define NKT    (K_DIM / KTILE)        // 32
#define ROWB   144                    // padded row bytes (72 fp16)
#define SECT_A (128 * ROWB)           // 18432
#define SECT_B (256 * ROWB)           // 36864
#define STAGE_BYTES (SECT_A + SECT_B) // 55296
#define NSTAGE 4
#define SMEM_TOTAL (NSTAGE * STAGE_BYTES)   // 221184 (216KB)

typedef __half f16;

// ===================== PTX helpers =====================
__device__ __forceinline__ uint32_t smem_u32(const void* p) {
    uint32_t a;
    asm("{ .reg .u64 t; cvta.to.shared.u64 t, %1; cvt.u32.u64 %0, t; }" : "=r"(a) : "l"(p));
    return a;
}
__device__ __forceinline__ void cp16(uint32_t smem, const void* g) {
    asm volatile("cp.async.cg.shared.global [%0], [%1], 16;" :: "r"(smem), "l"(g));
}
#define CP_COMMIT() asm volatile("cp.async.commit_group;" ::: "memory")
#define CP_WAIT(n)  asm volatile("cp.async.wait_group %0;" :: "n"(n) : "memory")

__device__ __forceinline__ void ldsm4(uint32_t& r0, uint32_t& r1, uint32_t& r2, uint32_t& r3,
                                      uint32_t addr) {
    asm volatile("ldmatrix.sync.aligned.m8n8.x4.shared.b16 {%0,%1,%2,%3}, [%4];"
                 : "=r"(r0), "=r"(r1), "=r"(r2), "=r"(r3) : "r"(addr));
}
__device__ __forceinline__ void mma16816(float& c0, float& c1, float& c2, float& c3,
                                         uint32_t a0, uint32_t a1, uint32_t a2, uint32_t a3,
                                         uint32_t b0, uint32_t b1) {
    asm volatile("mma.sync.aligned.m16n8k16.row.col.f32.f16.f16.f32 "
                 "{%0,%1,%2,%3}, {%4,%5,%6,%7}, {%8,%9}, {%0,%1,%2,%3};"
                 : "+f"(c0), "+f"(c1), "+f"(c2), "+f"(c3)
                 : "r"(a0), "r"(a1), "r"(a2), "r"(a3), "r"(b0), "r"(b1));
}

// ===================== scratch =====================
__device__ f16   g_kh[T_DIM * C_DIM];         // k fp16
__device__ f16   g_vh[T_DIM * C_DIM];         // v fp16
__device__ f16   g_rh[T_DIM * C_DIM];         // r fp16
__device__ float g_carryA[S_CHUNKS * C_DIM];
__device__ float g_carryB[S_CHUNKS * C_DIM];
__device__ float g_scanA[S_CHUNKS * C_DIM];
__device__ float g_scanB[S_CHUNKS * C_DIM];

__device__ f16 g_ax[3][T_DIM * K_DIM];   // mixed activations (fp16)
__device__ f16 g_wt[4][C_DIM * K_DIM];   // W^T [N,K] fp16
__device__ f16 g_g[T_DIM * C_DIM];       // gated output (fp16)

// ===================== fused pre-pass: mix + 4 weight transposes =====================
// blocks [0, 8192): mix;  blocks [8192, 24576): wsplit (4096 per weight)
__global__ void prep(const float* __restrict__ x,  const float* __restrict__ mk,
                     const float* __restrict__ mv, const float* __restrict__ mr,
                     const float* __restrict__ Wk, const float* __restrict__ Wv,
                     const float* __restrict__ Wr, const float* __restrict__ Wo)
{
    __shared__ float t[32][33];
    const int tid = threadIdx.x;
    if (blockIdx.x < 8192) {
        int idx = blockIdx.x * 256 + tid;
        int m  = idx >> 9;
        int c4 = (idx & 511) << 2;
        size_t off = (size_t)m * C_DIM + c4;
        float4 xc = *(const float4*)(x + off);
        float4 xp = make_float4(0.f, 0.f, 0.f, 0.f);
        if (m > 0) xp = *(const float4*)(x + off - C_DIM);
        const float* mixes[3] = { mk, mv, mr };
#pragma unroll
        for (int p = 0; p < 3; p++) {
            float4 mx = *(const float4*)(mixes[p] + c4);
            f16 h[4];
            h[0] = __float2half_rn(xc.x * mx.x + xp.x * (1.f - mx.x));
            h[1] = __float2half_rn(xc.y * mx.y + xp.y * (1.f - mx.y));
            h[2] = __float2half_rn(xc.z * mx.z + xp.z * (1.f - mx.z));
            h[3] = __float2half_rn(xc.w * mx.w + xp.w * (1.f - mx.w));
            *(uint2*)(&g_ax[p][off]) = *(uint2*)h;
        }
    } else {
        int id   = blockIdx.x - 8192;          // 0..16383
        int which = id >> 12;                   // 0..3
        int rem  = id & 4095;
        int n0 = (rem & 63) << 5;
        int k0 = (rem >> 6) << 5;
        const float* W = (which == 0) ? Wk : (which == 1) ? Wv : (which == 2) ? Wr : Wo;
        int tx = tid & 31, ty = tid >> 5;       // 32 x 8
#pragma unroll
        for (int i = 0; i < 32; i += 8)
            t[ty + i][tx] = W[(size_t)(k0 + ty + i) * C_DIM + n0 + tx];
        __syncthreads();
#pragma unroll
        for (int i = 0; i < 32; i += 8)
            g_wt[which][(size_t)(n0 + ty + i) * K_DIM + k0 + tx] =
                __float2half_rn(t[tx][ty + i]);
    }
}

// ===================== HMMA GEMM (fp16, CTA 128x256, frag double-buffer) =====
__device__ __forceinline__ void load_stage(
    uint32_t sb, int slot, int kt, int m0, int n0, int tid,
    const f16* __restrict__ A, const f16* __restrict__ B)
{
    const int k0 = kt * KTILE;
    uint32_t base = sb + slot * STAGE_BYTES;
#pragma unroll
    for (int t = 0; t < 6; t++) {
        int id = tid + t * 512;             // 0..3071
        int ch = (id & 7) << 3;             // fp16 units: 0,8,...,56
        uint32_t so;
        const f16* src;
        int grow;
        if (id < 1024) {                    // A: 128 rows
            int row = id >> 3;
            so   = base + row * ROWB + ch * 2;
            src  = A;
            grow = m0 + row;
        } else {                            // B: 256 rows
            int row = (id - 1024) >> 3;
            so   = base + SECT_A + row * ROWB + ch * 2;
            src  = B;
            grow = n0 + row;
        }
        cp16(so, src + (size_t)grow * K_DIM + k0 + ch);
    }
    CP_COMMIT();
}

struct Frag {
    uint32_t a[2][4];
    uint32_t b[16];
};

__device__ __forceinline__ void ld_frags(Frag& f, uint32_t abase, uint32_t bbase, int kk)
{
    uint32_t ao = abase + kk * 32;
    uint32_t bo = bbase + kk * 32;
#pragma unroll
    for (int mi = 0; mi < 2; mi++)
        ldsm4(f.a[mi][0], f.a[mi][1], f.a[mi][2], f.a[mi][3], ao + mi * 16 * ROWB);
#pragma unroll
    for (int q = 0; q < 4; q++)
        ldsm4(f.b[q * 4], f.b[q * 4 + 1], f.b[q * 4 + 2], f.b[q * 4 + 3],
              bo + q * 16 * ROWB);
}

__device__ __forceinline__ void compute_frag(const Frag& f, float acc[2][8][4])
{
#pragma unroll
    for (int mi = 0; mi < 2; mi++) {
#pragma unroll
        for (int nt = 0; nt < 8; nt++) {
            int i0 = (nt >> 1) * 4 + (nt & 1);
            float* c = acc[mi][nt];
            mma16816(c[0], c[1], c[2], c[3],
                     f.a[mi][0], f.a[mi][1], f.a[mi][2], f.a[mi][3],
                     f.b[i0], f.b[i0 + 2]);
        }
    }
}

__device__ __forceinline__ void gemm_body(
    const f16* __restrict__ A, const f16* __restrict__ B,
    float* __restrict__ Cf, f16* __restrict__ Ch, int half_out)
{
    extern __shared__ __align__(128) char smem[];
    uint32_t sb = smem_u32(smem);
    const int tid = threadIdx.x;
    const int wid = tid >> 5, lane = tid & 31;
    const int warp_m = wid >> 2;
    const int warp_n = wid & 3;
    const int m0 = blockIdx.y * 128;
    const int n0 = blockIdx.x * 256;

    float acc[2][8][4];
#pragma unroll
    for (int i = 0; i < 2; i++)
#pragma unroll
        for (int j = 0; j < 8; j++)
#pragma unroll
            for (int q = 0; q < 4; q++) acc[i][j][q] = 0.f;

    load_stage(sb, 0, 0, m0, n0, tid, A, B);
    load_stage(sb, 1, 1, m0, n0, tid, A, B);
    load_stage(sb, 2, 2, m0, n0, tid, A, B);

    const uint32_t lrow = lane & 15;
    const uint32_t lcol = (lane >> 4) << 3;
    const uint32_t aoff = (warp_m * 32 + lrow) * ROWB + lcol * 2;
    const uint32_t boff = SECT_A + (warp_n * 64 + lrow) * ROWB + lcol * 2;

    Frag fr[2];

    for (int kt = 0; kt < NKT; kt++) {
        const int s = kt & 3;
        CP_WAIT(2);
        __syncthreads();

        uint32_t stage = sb + s * STAGE_BYTES;
        uint32_t abase = stage + aoff;
        uint32_t bbase = stage + boff;

        ld_frags(fr[0], abase, bbase, 0);

        if (kt + 3 < NKT)
            load_stage(sb, (kt + 3) & 3, kt + 3, m0, n0, tid, A, B);
        else
            CP_COMMIT();

#pragma unroll
        for (int kk = 0; kk < 4; kk++) {
            if (kk < 3)
                ld_frags(fr[(kk + 1) & 1], abase, bbase, kk + 1);
            compute_frag(fr[kk & 1], acc);
        }
    }

    const int er = lane >> 2;
    const int ec = (lane & 3) * 2;
    if (!half_out) {
#pragma unroll
        for (int mi = 0; mi < 2; mi++)
#pragma unroll
            for (int nt = 0; nt < 8; nt++) {
                int r = m0 + warp_m * 32 + mi * 16 + er;
                int c = n0 + warp_n * 64 + nt * 8 + ec;
                float* c0 = Cf + (size_t)r * 2048 + c;
                *(float2*)c0              = make_float2(acc[mi][nt][0], acc[mi][nt][1]);
                *(float2*)(c0 + 8 * 2048) = make_float2(acc[mi][nt][2], acc[mi][nt][3]);
            }
    } else {
#pragma unroll
        for (int mi = 0; mi < 2; mi++)
#pragma unroll
            for (int nt = 0; nt < 8; nt++) {
                int r = m0 + warp_m * 32 + mi * 16 + er;
                int c = n0 + warp_n * 64 + nt * 8 + ec;
                f16* c0 = Ch + (size_t)r * 2048 + c;
                __half2 h0, h1;
                h0.x = __float2half_rn(acc[mi][nt][0]);
                h0.y = __float2half_rn(acc[mi][nt][1]);
                h1.x = __float2half_rn(acc[mi][nt][2]);
                h1.y = __float2half_rn(acc[mi][nt][3]);
                *(__half2*)c0              = h0;
                *(__half2*)(c0 + 8 * 2048) = h1;
            }
    }
}

__global__ void __launch_bounds__(512) gemm_qkv()
{
    int p = blockIdx.z;
    f16* C = (p == 0) ? g_kh : (p == 1) ? g_vh : g_rh;
    gemm_body(g_ax[p], g_wt[p], nullptr, C, 1);
}

__global__ void __launch_bounds__(512) gemm_out(float* __restrict__ out)
{
    gemm_body(g_g, g_wt[3], out, nullptr, 0);
}

// ===================== WKV chunked scan (2 channels/thread, half2) =====================
__global__ void wkv_pass1(const float* __restrict__ tdecay)
{
    int s = blockIdx.x >> 2;                         // chunk
    int p = ((blockIdx.x & 3) << 8) + threadIdx.x;   // pair 0..1023
    int c = p << 1;
    float d0 = __expf(-__expf(-__expf(tdecay[c])));
    float d1 = __expf(-__expf(-__expf(tdecay[c + 1])));
    const __half2* k2 = (const __half2*)g_kh;
    const __half2* v2 = (const __half2*)g_vh;
    float A0 = 0.f, B0 = 0.f, A1 = 0.f, B1 = 0.f;
    int base = s * L_CHUNK;
    for (int j = 0; j < L_CHUNK; j++) {
        size_t off = (size_t)(base + j) * 1024 + p;
        float2 kk = __half22float2(k2[off]);
        float2 vv = __half22float2(v2[off]);
        float e0 = __expf(kk.x), e1 = __expf(kk.y);
        A0 = d0 * A0 + e0 * vv.x;  B0 = d0 * B0 + e0;
        A1 = d1 * A1 + e1 * vv.y;  B1 = d1 * B1 + e1;
    }
    g_carryA[s * C_DIM + c] = A0;  g_carryA[s * C_DIM + c + 1] = A1;
    g_carryB[s * C_DIM + c] = B0;  g_carryB[s * C_DIM + c + 1] = B1;
}

__global__ void wkv_pass2(const float* __restrict__ tdecay)
{
    int c = blockIdx.x * 256 + threadIdx.x;
    float q = __expf(-__expf(tdecay[c]));
    float dL = __expf(-q * (float)L_CHUNK);
    float A = 0.f, B = 0.f;
    for (int s = 0; s < S_CHUNKS; s++) {
        g_scanA[s * C_DIM + c] = A;
        g_scanB[s * C_DIM + c] = B;
        A = dL * A + g_carryA[s * C_DIM + c];
        B = dL * B + g_carryB[s * C_DIM + c];
    }
}

__global__ void wkv_pass3(const float* __restrict__ tdecay,
                          const float* __restrict__ tfirst)
{
    int s = blockIdx.x >> 2;
    int p = ((blockIdx.x & 3) << 8) + threadIdx.x;
    int c = p << 1;
    float d0 = __expf(-__expf(-__expf(tdecay[c])));
    float d1 = __expf(-__expf(-__expf(tdecay[c + 1])));
    float eu0 = __expf(tfirst[c]), eu1 = __expf(tfirst[c + 1]);
    float A0 = g_scanA[s * C_DIM + c], A1 = g_scanA[s * C_DIM + c + 1];
    float B0 = g_scanB[s * C_DIM + c], B1 = g_scanB[s * C_DIM + c + 1];
    const __half2* k2 = (const __half2*)g_kh;
    const __half2* v2 = (const __half2*)g_vh;
    const __half2* r2 = (const __half2*)g_rh;
    __half2* g2 = (__half2*)g_g;
    int base = s * L_CHUNK;
    for (int j = 0; j < L_CHUNK; j++) {
        size_t off = (size_t)(base + j) * 1024 + p;
        float2 kk = __half22float2(k2[off]);
        float2 vv = __half22float2(v2[off]);
        float2 rr = __half22float2(r2[off]);
        float e0 = __expf(kk.x), e1 = __expf(kk.y);
        float eue0 = eu0 * e0, eue1 = eu1 * e1;
        float w0 = (A0 + eue0 * vv.x) / (B0 + eue0);
        float w1 = (A1 + eue1 * vv.y) / (B1 + eue1);
        float s0 = 1.f / (1.f + __expf(-rr.x));
        float s1 = 1.f / (1.f + __expf(-rr.y));
        __half2 g;
        g.x = __float2half_rn(s0 * w0);
        g.y = __float2half_rn(s1 * w1);
        g2[off] = g;
        A0 = d0 * A0 + e0 * vv.x;  B0 = d0 * B0 + e0;
        A1 = d1 * A1 + e1 * vv.y;  B1 = d1 * B1 + e1;
    }
}

// ===================== launch =====================
extern "C" void kernel_launch(void* const* d_in, const int* in_sizes, int n_in,
                              void* d_out, int out_size)
{
    const float* x  = (const float*)d_in[0];
    const float* tf = (const float*)d_in[1];
    const float* td = (const float*)d_in[2];
    const float* mk = (const float*)d_in[3];
    const float* mv = (const float*)d_in[4];
    const float* mr = (const float*)d_in[5];
    const float* Wk = (const float*)d_in[6];
    const float* Wv = (const float*)d_in[7];
    const float* Wr = (const float*)d_in[8];
    const float* Wo = (const float*)d_in[9];
    float* out = (float*)d_out;

    cudaFuncSetAttribute(gemm_qkv, cudaFuncAttributeMaxDynamicSharedMemorySize, SMEM_TOTAL);
    cudaFuncSetAttribute(gemm_out, cudaFuncAttributeMaxDynamicSharedMemorySize, SMEM_TOTAL);

    // 1: fused pre-pass (mix + 4 weight transposes)
    prep<<<24576, 256>>>(x, mk, mv, mr, Wk, Wv, Wr, Wo);

    // 2: fused k/v/r projections
    dim3 gqkv(C_DIM / 256, T_DIM / 128, 3);
    gemm_qkv<<<gqkv, 512, SMEM_TOTAL>>>();

    // 3-5: WKV scan + gate
    wkv_pass1<<<S_CHUNKS * 4, 256>>>(td);
    wkv_pass2<<<C_DIM / 256, 256>>>(td);
    wkv_pass3<<<S_CHUNKS * 4, 256>>>(td, tf);

    // 6: output projection
    dim3 go(C_DIM / 256, T_DIM / 128);
    gemm_out<<<go, 512, SMEM_TOTAL>>>(out);
}

// round 11
// speedup vs baseline: 1.0397x; 1.0397x over previous
#include <cuda_runtime.h>
#include <cuda_fp16.h>
#include <cstdint>

#define T_DIM  4096
#define C_DIM  2048
#define K_DIM  2048
#define S_CHUNKS 32
#define L_CHUNK  128

#define KTILE  64
#define NKT    (K_DIM / KTILE)        // 32
#define ROWB   144                    // padded row bytes (72 fp16)
#define SECT_A (128 * ROWB)           // 18432
#define SECT_B (256 * ROWB)           // 36864
#define STAGE_BYTES (SECT_A + SECT_B) // 55296
#define NSTAGE 4
#define SMEM_TOTAL (NSTAGE * STAGE_BYTES)   // 221184 (216KB)

typedef __half f16;

// ===================== PTX helpers =====================
__device__ __forceinline__ uint32_t smem_u32(const void* p) {
    uint32_t a;
    asm("{ .reg .u64 t; cvta.to.shared.u64 t, %1; cvt.u32.u64 %0, t; }" : "=r"(a) : "l"(p));
    return a;
}
__device__ __forceinline__ void cp16(uint32_t smem, const void* g) {
    asm volatile("cp.async.cg.shared.global [%0], [%1], 16;" :: "r"(smem), "l"(g));
}
#define CP_COMMIT() asm volatile("cp.async.commit_group;" ::: "memory")
#define CP_WAIT(n)  asm volatile("cp.async.wait_group %0;" :: "n"(n) : "memory")

__device__ __forceinline__ void ldsm4(uint32_t& r0, uint32_t& r1, uint32_t& r2, uint32_t& r3,
                                      uint32_t addr) {
    asm volatile("ldmatrix.sync.aligned.m8n8.x4.shared.b16 {%0,%1,%2,%3}, [%4];"
                 : "=r"(r0), "=r"(r1), "=r"(r2), "=r"(r3) : "r"(addr));
}
__device__ __forceinline__ void mma16816(float& c0, float& c1, float& c2, float& c3,
                                         uint32_t a0, uint32_t a1, uint32_t a2, uint32_t a3,
                                         uint32_t b0, uint32_t b1) {
    asm volatile("mma.sync.aligned.m16n8k16.row.col.f32.f16.f16.f32 "
                 "{%0,%1,%2,%3}, {%4,%5,%6,%7}, {%8,%9}, {%0,%1,%2,%3};"
                 : "+f"(c0), "+f"(c1), "+f"(c2), "+f"(c3)
                 : "r"(a0), "r"(a1), "r"(a2), "r"(a3), "r"(b0), "r"(b1));
}

// ===================== scratch =====================
__device__ f16   g_kh[T_DIM * C_DIM];
__device__ f16   g_vh[T_DIM * C_DIM];
__device__ f16   g_rh[T_DIM * C_DIM];
__device__ float g_carryA[S_CHUNKS * C_DIM];
__device__ float g_carryB[S_CHUNKS * C_DIM];

__device__ f16 g_ax[3][T_DIM * K_DIM];   // mixed activations (fp16)
__device__ f16 g_wt[4][C_DIM * K_DIM];   // W^T [N,K] fp16
__device__ f16 g_g[T_DIM * C_DIM];       // gated output (fp16)

// ===================== pre-pass: mix to fp16 =====================
__global__ void mix_split(const float* __restrict__ x, const float* __restrict__ mk,
                          const float* __restrict__ mv, const float* __restrict__ mr)
{
    int idx = blockIdx.x * 256 + threadIdx.x;
    int m  = idx >> 9;
    int c4 = (idx & 511) << 2;
    size_t off = (size_t)m * C_DIM + c4;
    float4 xc = *(const float4*)(x + off);
    float4 xp = make_float4(0.f, 0.f, 0.f, 0.f);
    if (m > 0) xp = *(const float4*)(x + off - C_DIM);
    const float* mixes[3] = { mk, mv, mr };
#pragma unroll
    for (int p = 0; p < 3; p++) {
        float4 mx = *(const float4*)(mixes[p] + c4);
        f16 h[4];
        h[0] = __float2half_rn(xc.x * mx.x + xp.x * (1.f - mx.x));
        h[1] = __float2half_rn(xc.y * mx.y + xp.y * (1.f - mx.y));
        h[2] = __float2half_rn(xc.z * mx.z + xp.z * (1.f - mx.z));
        h[3] = __float2half_rn(xc.w * mx.w + xp.w * (1.f - mx.w));
        *(uint2*)(&g_ax[p][off]) = *(uint2*)h;
    }
}

// ===================== pre-pass: weight transpose to fp16 [N,K] =====================
__global__ void wsplit_pair(const float* __restrict__ W0, const float* __restrict__ W1,
                            int base)
{
    __shared__ float t[32][33];
    const float* W = (blockIdx.z == 0) ? W0 : W1;
    int which = base + blockIdx.z;
    int n0 = blockIdx.x * 32, k0 = blockIdx.y * 32;
    int tx = threadIdx.x, ty = threadIdx.y;
#pragma unroll
    for (int i = 0; i < 32; i += 8)
        t[ty + i][tx] = W[(size_t)(k0 + ty + i) * C_DIM + n0 + tx];
    __syncthreads();
#pragma unroll
    for (int i = 0; i < 32; i += 8)
        g_wt[which][(size_t)(n0 + ty + i) * K_DIM + k0 + tx] =
            __float2half_rn(t[tx][ty + i]);
}

// ===================== HMMA GEMM (fp16, CTA 128x256, frag double-buffer) =====
__device__ __forceinline__ void load_stage(
    uint32_t sb, int slot, int kt, int m0, int n0, int tid,
    const f16* __restrict__ A, const f16* __restrict__ B)
{
    const int k0 = kt * KTILE;
    uint32_t base = sb + slot * STAGE_BYTES;
#pragma unroll
    for (int t = 0; t < 6; t++) {
        int id = tid + t * 512;             // 0..3071
        int ch = (id & 7) << 3;
        uint32_t so;
        const f16* src;
        int grow;
        if (id < 1024) {                    // A: 128 rows
            int row = id >> 3;
            so   = base + row * ROWB + ch * 2;
            src  = A;
            grow = m0 + row;
        } else {                            // B: 256 rows
            int row = (id - 1024) >> 3;
            so   = base + SECT_A + row * ROWB + ch * 2;
            src  = B;
            grow = n0 + row;
        }
        cp16(so, src + (size_t)grow * K_DIM + k0 + ch);
    }
    CP_COMMIT();
}

struct Frag {
    uint32_t a[2][4];
    uint32_t b[16];
};

__device__ __forceinline__ void ld_frags(Frag& f, uint32_t abase, uint32_t bbase, int kk)
{
    uint32_t ao = abase + kk * 32;
    uint32_t bo = bbase + kk * 32;
#pragma unroll
    for (int mi = 0; mi < 2; mi++)
        ldsm4(f.a[mi][0], f.a[mi][1], f.a[mi][2], f.a[mi][3], ao + mi * 16 * ROWB);
#pragma unroll
    for (int q = 0; q < 4; q++)
        ldsm4(f.b[q * 4], f.b[q * 4 + 1], f.b[q * 4 + 2], f.b[q * 4 + 3],
              bo + q * 16 * ROWB);
}

__device__ __forceinline__ void compute_frag(const Frag& f, float acc[2][8][4])
{
#pragma unroll
    for (int mi = 0; mi < 2; mi++) {
#pragma unroll
        for (int nt = 0; nt < 8; nt++) {
            int i0 = (nt >> 1) * 4 + (nt & 1);
            float* c = acc[mi][nt];
            mma16816(c[0], c[1], c[2], c[3],
                     f.a[mi][0], f.a[mi][1], f.a[mi][2], f.a[mi][3],
                     f.b[i0], f.b[i0 + 2]);
        }
    }
}

__device__ __forceinline__ void gemm_body(
    const f16* __restrict__ A, const f16* __restrict__ B,
    float* __restrict__ Cf, f16* __restrict__ Ch, int half_out)
{
    extern __shared__ __align__(128) char smem[];
    uint32_t sb = smem_u32(smem);
    const int tid = threadIdx.x;
    const int wid = tid >> 5, lane = tid & 31;
    const int warp_m = wid >> 2;
    const int warp_n = wid & 3;
    const int m0 = blockIdx.y * 128;
    const int n0 = blockIdx.x * 256;

    float acc[2][8][4];
#pragma unroll
    for (int i = 0; i < 2; i++)
#pragma unroll
        for (int j = 0; j < 8; j++)
#pragma unroll
            for (int q = 0; q < 4; q++) acc[i][j][q] = 0.f;

    load_stage(sb, 0, 0, m0, n0, tid, A, B);
    load_stage(sb, 1, 1, m0, n0, tid, A, B);
    load_stage(sb, 2, 2, m0, n0, tid, A, B);

    const uint32_t lrow = lane & 15;
    const uint32_t lcol = (lane >> 4) << 3;
    const uint32_t aoff = (warp_m * 32 + lrow) * ROWB + lcol * 2;
    const uint32_t boff = SECT_A + (warp_n * 64 + lrow) * ROWB + lcol * 2;

    Frag fr[2];

    for (int kt = 0; kt < NKT; kt++) {
        const int s = kt & 3;
        CP_WAIT(2);
        __syncthreads();

        uint32_t stage = sb + s * STAGE_BYTES;
        uint32_t abase = stage + aoff;
        uint32_t bbase = stage + boff;

        ld_frags(fr[0], abase, bbase, 0);

        if (kt + 3 < NKT)
            load_stage(sb, (kt + 3) & 3, kt + 3, m0, n0, tid, A, B);
        else
            CP_COMMIT();

#pragma unroll
        for (int kk = 0; kk < 4; kk++) {
            if (kk < 3)
                ld_frags(fr[(kk + 1) & 1], abase, bbase, kk + 1);
            compute_frag(fr[kk & 1], acc);
        }
    }

    const int er = lane >> 2;
    const int ec = (lane & 3) * 2;
    if (!half_out) {
#pragma unroll
        for (int mi = 0; mi < 2; mi++)
#pragma unroll
            for (int nt = 0; nt < 8; nt++) {
                int r = m0 + warp_m * 32 + mi * 16 + er;
                int c = n0 + warp_n * 64 + nt * 8 + ec;
                float* c0 = Cf + (size_t)r * 2048 + c;
                *(float2*)c0              = make_float2(acc[mi][nt][0], acc[mi][nt][1]);
                *(float2*)(c0 + 8 * 2048) = make_float2(acc[mi][nt][2], acc[mi][nt][3]);
            }
    } else {
#pragma unroll
        for (int mi = 0; mi < 2; mi++)
#pragma unroll
            for (int nt = 0; nt < 8; nt++) {
                int r = m0 + warp_m * 32 + mi * 16 + er;
                int c = n0 + warp_n * 64 + nt * 8 + ec;
                f16* c0 = Ch + (size_t)r * 2048 + c;
                __half2 h0, h1;
                h0.x = __float2half_rn(acc[mi][nt][0]);
                h0.y = __float2half_rn(acc[mi][nt][1]);
                h1.x = __float2half_rn(acc[mi][nt][2]);
                h1.y = __float2half_rn(acc[mi][nt][3]);
                *(__half2*)c0              = h0;
                *(__half2*)(c0 + 8 * 2048) = h1;
            }
    }
}

__global__ void __launch_bounds__(512) gemm_qkv()
{
    int p = blockIdx.z;
    f16* C = (p == 0) ? g_kh : (p == 1) ? g_vh : g_rh;
    gemm_body(g_ax[p], g_wt[p], nullptr, C, 1);
}

__global__ void __launch_bounds__(512) gemm_out(float* __restrict__ out)
{
    gemm_body(g_g, g_wt[3], out, nullptr, 0);
}

// ===================== WKV chunked scan (2-pass; prefix folded into pass3) ===
__global__ void wkv_pass1(const float* __restrict__ tdecay)
{
    int s = blockIdx.x >> 3;
    int c = ((blockIdx.x & 7) << 8) + threadIdx.x;
    float q = __expf(-__expf(tdecay[c]));
    float d = __expf(-q);
    float A = 0.f, B = 0.f;
    int base = s * L_CHUNK;
    for (int j = 0; j < L_CHUNK; j++) {
        size_t off = (size_t)(base + j) * C_DIM + c;
        float e = __expf(__half2float(g_kh[off]));
        float vv = __half2float(g_vh[off]);
        A = d * A + e * vv;
        B = d * B + e;
    }
    g_carryA[s * C_DIM + c] = A;
    g_carryB[s * C_DIM + c] = B;
}

__global__ void wkv_pass3(const float* __restrict__ tdecay,
                          const float* __restrict__ tfirst)
{
    int s = blockIdx.x >> 3;
    int c = ((blockIdx.x & 7) << 8) + threadIdx.x;
    float q = __expf(-__expf(tdecay[c]));
    float d = __expf(-q);
    float dL = __expf(-q * (float)L_CHUNK);
    float eu = __expf(tfirst[c]);

    // chunk prefix from per-chunk carries (loads are independent -> MLP)
    float A = 0.f, B = 0.f;
    for (int t = 0; t < s; t++) {
        A = dL * A + g_carryA[t * C_DIM + c];
        B = dL * B + g_carryB[t * C_DIM + c];
    }

    int base = s * L_CHUNK;
    for (int j = 0; j < L_CHUNK; j++) {
        size_t off = (size_t)(base + j) * C_DIM + c;
        float kk = __half2float(g_kh[off]);
        float vv = __half2float(g_vh[off]);
        float rr = __half2float(g_rh[off]);
        float e = __expf(kk);
        float eue = eu * e;
        float wkv = (A + eue * vv) / (B + eue);
        float sr = 1.f / (1.f + __expf(-rr));
        g_g[off] = __float2half_rn(sr * wkv);
        A = d * A + e * vv;
        B = d * B + e;
    }
}

// ===================== launch =====================
extern "C" void kernel_launch(void* const* d_in, const int* in_sizes, int n_in,
                              void* d_out, int out_size)
{
    const float* x  = (const float*)d_in[0];
    const float* tf = (const float*)d_in[1];
    const float* td = (const float*)d_in[2];
    const float* mk = (const float*)d_in[3];
    const float* mv = (const float*)d_in[4];
    const float* mr = (const float*)d_in[5];
    const float* Wk = (const float*)d_in[6];
    const float* Wv = (const float*)d_in[7];
    const float* Wr = (const float*)d_in[8];
    const float* Wo = (const float*)d_in[9];
    float* out = (float*)d_out;

    cudaFuncSetAttribute(gemm_qkv, cudaFuncAttributeMaxDynamicSharedMemorySize, SMEM_TOTAL);
    cudaFuncSetAttribute(gemm_out, cudaFuncAttributeMaxDynamicSharedMemorySize, SMEM_TOTAL);

    // 1: mix to fp16
    mix_split<<<(T_DIM * C_DIM / 4) / 256, 256>>>(x, mk, mv, mr);
    // 2,3: weight transpose
    dim3 wgrid(C_DIM / 32, K_DIM / 32, 2), wblk(32, 8);
    wsplit_pair<<<wgrid, wblk>>>(Wk, Wv, 0);
    wsplit_pair<<<wgrid, wblk>>>(Wr, Wo, 2);

    // 4: fused k/v/r projections (profiled launch)
    dim3 gqkv(C_DIM / 256, T_DIM / 128, 3);
    gemm_qkv<<<gqkv, 512, SMEM_TOTAL>>>();

    // 5,6: WKV scan + gate (prefix folded into pass3)
    wkv_pass1<<<S_CHUNKS * (C_DIM / 256), 256>>>(td);
    wkv_pass3<<<S_CHUNKS * (C_DIM / 256), 256>>>(td, tf);

    // 7: output projection
    dim3 go(C_DIM / 256, T_DIM / 128);
    gemm_out<<<go, 512, SMEM_TOTAL>>>(out);
}

// round 12
// speedup vs baseline: 1.0764x; 1.0353x over previous
#include <cuda_runtime.h>
#include <cuda_fp16.h>
#include <cstdint>

#define T_DIM  4096
#define C_DIM  2048
#define K_DIM  2048
#define S_CHUNKS 32
#define L_CHUNK  128

#define KTILE  64
#define NKT    (K_DIM / KTILE)        // 32
#define ROWB   144                    // padded row bytes (72 fp16)
#define SECT   (128 * ROWB)           // 18432 (A or B section, 128 rows)
#define STAGE_BYTES (2 * SECT)        // 36864
#define NSTAGE 3
#define SMEM_TOTAL (NSTAGE * STAGE_BYTES)   // 110592 (108KB) -> 2 CTAs/SM

typedef __half f16;

// ===================== PTX helpers =====================
__device__ __forceinline__ uint32_t smem_u32(const void* p) {
    uint32_t a;
    asm("{ .reg .u64 t; cvta.to.shared.u64 t, %1; cvt.u32.u64 %0, t; }" : "=r"(a) : "l"(p));
    return a;
}
__device__ __forceinline__ void cp16(uint32_t smem, const void* g) {
    asm volatile("cp.async.cg.shared.global [%0], [%1], 16;" :: "r"(smem), "l"(g));
}
#define CP_COMMIT() asm volatile("cp.async.commit_group;" ::: "memory")
#define CP_WAIT(n)  asm volatile("cp.async.wait_group %0;" :: "n"(n) : "memory")

__device__ __forceinline__ void ldsm4(uint32_t& r0, uint32_t& r1, uint32_t& r2, uint32_t& r3,
                                      uint32_t addr) {
    asm volatile("ldmatrix.sync.aligned.m8n8.x4.shared.b16 {%0,%1,%2,%3}, [%4];"
                 : "=r"(r0), "=r"(r1), "=r"(r2), "=r"(r3) : "r"(addr));
}
__device__ __forceinline__ void mma16816(float& c0, float& c1, float& c2, float& c3,
                                         uint32_t a0, uint32_t a1, uint32_t a2, uint32_t a3,
                                         uint32_t b0, uint32_t b1) {
    asm volatile("mma.sync.aligned.m16n8k16.row.col.f32.f16.f16.f32 "
                 "{%0,%1,%2,%3}, {%4,%5,%6,%7}, {%8,%9}, {%0,%1,%2,%3};"
                 : "+f"(c0), "+f"(c1), "+f"(c2), "+f"(c3)
                 : "r"(a0), "r"(a1), "r"(a2), "r"(a3), "r"(b0), "r"(b1));
}

// ===================== scratch =====================
__device__ f16   g_kh[T_DIM * C_DIM];
__device__ f16   g_vh[T_DIM * C_DIM];
__device__ f16   g_rh[T_DIM * C_DIM];
__device__ float g_carryA[S_CHUNKS * C_DIM];
__device__ float g_carryB[S_CHUNKS * C_DIM];

__device__ f16 g_ax[3][T_DIM * K_DIM];   // mixed activations (fp16)
__device__ f16 g_wt[4][C_DIM * K_DIM];   // W^T [N,K] fp16
__device__ f16 g_g[T_DIM * C_DIM];       // gated output (fp16)

// ===================== pre-pass: mix to fp16 =====================
__global__ void mix_split(const float* __restrict__ x, const float* __restrict__ mk,
                          const float* __restrict__ mv, const float* __restrict__ mr)
{
    int idx = blockIdx.x * 256 + threadIdx.x;
    int m  = idx >> 9;
    int c4 = (idx & 511) << 2;
    size_t off = (size_t)m * C_DIM + c4;
    float4 xc = *(const float4*)(x + off);
    float4 xp = make_float4(0.f, 0.f, 0.f, 0.f);
    if (m > 0) xp = *(const float4*)(x + off - C_DIM);
    const float* mixes[3] = { mk, mv, mr };
#pragma unroll
    for (int p = 0; p < 3; p++) {
        float4 mx = *(const float4*)(mixes[p] + c4);
        f16 h[4];
        h[0] = __float2half_rn(xc.x * mx.x + xp.x * (1.f - mx.x));
        h[1] = __float2half_rn(xc.y * mx.y + xp.y * (1.f - mx.y));
        h[2] = __float2half_rn(xc.z * mx.z + xp.z * (1.f - mx.z));
        h[3] = __float2half_rn(xc.w * mx.w + xp.w * (1.f - mx.w));
        *(uint2*)(&g_ax[p][off]) = *(uint2*)h;
    }
}

// ===================== pre-pass: weight transpose to fp16 [N,K] =====================
__global__ void wsplit_pair(const float* __restrict__ W0, const float* __restrict__ W1,
                            int base)
{
    __shared__ float t[32][33];
    const float* W = (blockIdx.z == 0) ? W0 : W1;
    int which = base + blockIdx.z;
    int n0 = blockIdx.x * 32, k0 = blockIdx.y * 32;
    int tx = threadIdx.x, ty = threadIdx.y;
#pragma unroll
    for (int i = 0; i < 32; i += 8)
        t[ty + i][tx] = W[(size_t)(k0 + ty + i) * C_DIM + n0 + tx];
    __syncthreads();
#pragma unroll
    for (int i = 0; i < 32; i += 8)
        g_wt[which][(size_t)(n0 + ty + i) * K_DIM + k0 + tx] =
            __float2half_rn(t[tx][ty + i]);
}

// ===================== HMMA GEMM (fp16, CTA 128x128, 2 CTAs/SM) =====
__device__ __forceinline__ void load_stage(
    uint32_t sb, int slot, int kt, int m0, int n0, int tid,
    const f16* __restrict__ A, const f16* __restrict__ B)
{
    const int k0 = kt * KTILE;
    uint32_t base = sb + slot * STAGE_BYTES;
#pragma unroll
    for (int t = 0; t < 4; t++) {
        int id = tid + t * 512;             // 0..2047
        int ch = (id & 7) << 3;             // fp16 units 0..56
        int row = (id & 1023) >> 3;
        uint32_t so = base + (id >> 10) * SECT + row * ROWB + ch * 2;
        const f16* src = (id < 1024) ? A : B;
        int grow = ((id < 1024) ? m0 : n0) + row;
        cp16(so, src + (size_t)grow * K_DIM + k0 + ch);
    }
    CP_COMMIT();
}

struct Frag {
    uint32_t a[2][4];
    uint32_t b[8];
};

__device__ __forceinline__ void ld_frags(Frag& f, uint32_t abase, uint32_t bbase, int kk)
{
    uint32_t ao = abase + kk * 32;
    uint32_t bo = bbase + kk * 32;
#pragma unroll
    for (int mi = 0; mi < 2; mi++)
        ldsm4(f.a[mi][0], f.a[mi][1], f.a[mi][2], f.a[mi][3], ao + mi * 16 * ROWB);
#pragma unroll
    for (int q = 0; q < 2; q++)
        ldsm4(f.b[q * 4], f.b[q * 4 + 1], f.b[q * 4 + 2], f.b[q * 4 + 3],
              bo + q * 16 * ROWB);
}

__device__ __forceinline__ void compute_frag(const Frag& f, float acc[2][4][4])
{
#pragma unroll
    for (int mi = 0; mi < 2; mi++) {
#pragma unroll
        for (int nt = 0; nt < 4; nt++) {
            int i0 = (nt >> 1) * 4 + (nt & 1);
            float* c = acc[mi][nt];
            mma16816(c[0], c[1], c[2], c[3],
                     f.a[mi][0], f.a[mi][1], f.a[mi][2], f.a[mi][3],
                     f.b[i0], f.b[i0 + 2]);
        }
    }
}

__device__ __forceinline__ void gemm_body(
    const f16* __restrict__ A, const f16* __restrict__ B,
    float* __restrict__ Cf, f16* __restrict__ Ch, int half_out)
{
    extern __shared__ __align__(128) char smem[];
    uint32_t sb = smem_u32(smem);
    const int tid = threadIdx.x;
    const int wid = tid >> 5, lane = tid & 31;
    const int warp_m = wid >> 2;           // 0..3 (32 rows each)
    const int warp_n = wid & 3;            // 0..3 (32 cols each)
    const int m0 = blockIdx.y * 128;
    const int n0 = blockIdx.x * 128;

    float acc[2][4][4];
#pragma unroll
    for (int i = 0; i < 2; i++)
#pragma unroll
        for (int j = 0; j < 4; j++)
#pragma unroll
            for (int q = 0; q < 4; q++) acc[i][j][q] = 0.f;

    load_stage(sb, 0, 0, m0, n0, tid, A, B);
    load_stage(sb, 1, 1, m0, n0, tid, A, B);

    const uint32_t lrow = lane & 15;
    const uint32_t lcol = (lane >> 4) << 3;
    const uint32_t aoff = (warp_m * 32 + lrow) * ROWB + lcol * 2;
    const uint32_t boff = SECT + (warp_n * 32 + lrow) * ROWB + lcol * 2;

    Frag fr[2];

    for (int kt = 0; kt < NKT; kt++) {
        const int s = kt % NSTAGE;
        CP_WAIT(1);
        __syncthreads();

        uint32_t stage = sb + s * STAGE_BYTES;
        uint32_t abase = stage + aoff;
        uint32_t bbase = stage + boff;

        ld_frags(fr[0], abase, bbase, 0);

        if (kt + 2 < NKT)
            load_stage(sb, (kt + 2) % NSTAGE, kt + 2, m0, n0, tid, A, B);
        else
            CP_COMMIT();

#pragma unroll
        for (int kk = 0; kk < 4; kk++) {
            if (kk < 3)
                ld_frags(fr[(kk + 1) & 1], abase, bbase, kk + 1);
            compute_frag(fr[kk & 1], acc);
        }
    }

    const int er = lane >> 2;
    const int ec = (lane & 3) * 2;
    if (!half_out) {
#pragma unroll
        for (int mi = 0; mi < 2; mi++)
#pragma unroll
            for (int nt = 0; nt < 4; nt++) {
                int r = m0 + warp_m * 32 + mi * 16 + er;
                int c = n0 + warp_n * 32 + nt * 8 + ec;
                float* c0 = Cf + (size_t)r * 2048 + c;
                *(float2*)c0              = make_float2(acc[mi][nt][0], acc[mi][nt][1]);
                *(float2*)(c0 + 8 * 2048) = make_float2(acc[mi][nt][2], acc[mi][nt][3]);
            }
    } else {
#pragma unroll
        for (int mi = 0; mi < 2; mi++)
#pragma unroll
            for (int nt = 0; nt < 4; nt++) {
                int r = m0 + warp_m * 32 + mi * 16 + er;
                int c = n0 + warp_n * 32 + nt * 8 + ec;
                f16* c0 = Ch + (size_t)r * 2048 + c;
                __half2 h0, h1;
                h0.x = __float2half_rn(acc[mi][nt][0]);
                h0.y = __float2half_rn(acc[mi][nt][1]);
                h1.x = __float2half_rn(acc[mi][nt][2]);
                h1.y = __float2half_rn(acc[mi][nt][3]);
                *(__half2*)c0              = h0;
                *(__half2*)(c0 + 8 * 2048) = h1;
            }
    }
}

__global__ void __launch_bounds__(512, 2) gemm_qkv()
{
    int p = blockIdx.z;
    f16* C = (p == 0) ? g_kh : (p == 1) ? g_vh : g_rh;
    gemm_body(g_ax[p], g_wt[p], nullptr, C, 1);
}

__global__ void __launch_bounds__(512, 2) gemm_out(float* __restrict__ out)
{
    gemm_body(g_g, g_wt[3], out, nullptr, 0);
}

// ===================== WKV chunked scan (2-pass; prefix folded into pass3) ===
__global__ void wkv_pass1(const float* __restrict__ tdecay)
{
    int s = blockIdx.x >> 3;
    int c = ((blockIdx.x & 7) << 8) + threadIdx.x;
    float q = __expf(-__expf(tdecay[c]));
    float d = __expf(-q);
    float A = 0.f, B = 0.f;
    int base = s * L_CHUNK;
    for (int j = 0; j < L_CHUNK; j++) {
        size_t off = (size_t)(base + j) * C_DIM + c;
        float e = __expf(__half2float(g_kh[off]));
        float vv = __half2float(g_vh[off]);
        A = d * A + e * vv;
        B = d * B + e;
    }
    g_carryA[s * C_DIM + c] = A;
    g_carryB[s * C_DIM + c] = B;
}

__global__ void wkv_pass3(const float* __restrict__ tdecay,
                          const float* __restrict__ tfirst)
{
    int s = blockIdx.x >> 3;
    int c = ((blockIdx.x & 7) << 8) + threadIdx.x;
    float q = __expf(-__expf(tdecay[c]));
    float d = __expf(-q);
    float dL = __expf(-q * (float)L_CHUNK);
    float eu = __expf(tfirst[c]);

    float A = 0.f, B = 0.f;
    for (int t = 0; t < s; t++) {
        A = dL * A + g_carryA[t * C_DIM + c];
        B = dL * B + g_carryB[t * C_DIM + c];
    }

    int base = s * L_CHUNK;
    for (int j = 0; j < L_CHUNK; j++) {
        size_t off = (size_t)(base + j) * C_DIM + c;
        float kk = __half2float(g_kh[off]);
        float vv = __half2float(g_vh[off]);
        float rr = __half2float(g_rh[off]);
        float e = __expf(kk);
        float eue = eu * e;
        float wkv = (A + eue * vv) / (B + eue);
        float sr = 1.f / (1.f + __expf(-rr));
        g_g[off] = __float2half_rn(sr * wkv);
        A = d * A + e * vv;
        B = d * B + e;
    }
}

// ===================== launch =====================
extern "C" void kernel_launch(void* const* d_in, const int* in_sizes, int n_in,
                              void* d_out, int out_size)
{
    const float* x  = (const float*)d_in[0];
    const float* tf = (const float*)d_in[1];
    const float* td = (const float*)d_in[2];
    const float* mk = (const float*)d_in[3];
    const float* mv = (const float*)d_in[4];
    const float* mr = (const float*)d_in[5];
    const float* Wk = (const float*)d_in[6];
    const float* Wv = (const float*)d_in[7];
    const float* Wr = (const float*)d_in[8];
    const float* Wo = (const float*)d_in[9];
    float* out = (float*)d_out;

    cudaFuncSetAttribute(gemm_qkv, cudaFuncAttributeMaxDynamicSharedMemorySize, SMEM_TOTAL);
    cudaFuncSetAttribute(gemm_out, cudaFuncAttributeMaxDynamicSharedMemorySize, SMEM_TOTAL);

    // 1: mix to fp16
    mix_split<<<(T_DIM * C_DIM / 4) / 256, 256>>>(x, mk, mv, mr);
    // 2,3: weight transpose
    dim3 wgrid(C_DIM / 32, K_DIM / 32, 2), wblk(32, 8);
    wsplit_pair<<<wgrid, wblk>>>(Wk, Wv, 0);
    wsplit_pair<<<wgrid, wblk>>>(Wr, Wo, 2);

    // 4: fused k/v/r projections (profiled launch)
    dim3 gqkv(C_DIM / 128, T_DIM / 128, 3);   // (16, 32, 3) = 1536 CTAs
    gemm_qkv<<<gqkv, 512, SMEM_TOTAL>>>();

    // 5,6: WKV scan + gate
    wkv_pass1<<<S_CHUNKS * (C_DIM / 256), 256>>>(td);
    wkv_pass3<<<S_CHUNKS * (C_DIM / 256), 256>>>(td, tf);

    // 7: output projection
    dim3 go(C_DIM / 128, T_DIM / 128);        // (16, 32) = 512 CTAs
    gemm_out<<<go, 512, SMEM_TOTAL>>>(out);
}